// round 3
// baseline (speedup 1.0000x reference)
#include <cuda_runtime.h>
#include <math_constants.h>

// Fixed shapes per reference setup_inputs
#define BATCH   8
#define NPTS    8192
#define NQ      (2 * BATCH * NPTS)     // 131072 queries total
#define EPSF    1e-12f

// Grid parameters
#define G       32
#define NCELLS  (G * G * G)            // 32768
#define GLO     (-4.0f)
#define H       0.25f
#define INVH    4.0f
#define NCLOUD  16                     // 2 inputs x 8 batches

// Scratch (no cudaMalloc allowed)
__device__ float4 g_pts[NCLOUD][NPTS];          // cell-sorted records (x,y,z,|p|^2)
__device__ int    g_oidx[NCLOUD][NPTS];         // original in-batch index of sorted point
__device__ int    g_hist[NCLOUD][NCELLS];       // per-cell counts
__device__ int    g_cellstart[NCLOUD][NCELLS + 1];
__device__ int    g_cursor[NCLOUD][NCELLS];     // scatter cursors
__device__ float  g_dist[NCLOUD][NPTS];         // per-original-index NN distance
__device__ float  g_bsum[128];                  // block partial sums

__device__ __forceinline__ int cell_coord(float v) {
    int c = (int)((v - GLO) * INVH);
    return min(max(c, 0), G - 1);
}

// ---------------- setup ----------------

__global__ void zero_kernel() {
    int idx = blockIdx.x * blockDim.x + threadIdx.x;   // 0 .. NCLOUD*NCELLS-1
    ((int*)g_hist)[idx] = 0;
}

__global__ void hist_kernel(const float* __restrict__ xyz1,
                            const float* __restrict__ xyz2) {
    int idx = blockIdx.x * blockDim.x + threadIdx.x;   // 0 .. NQ-1
    int s      = idx / (BATCH * NPTS);
    int within = idx - s * (BATCH * NPTS);
    const float* p = ((s == 0) ? xyz1 : xyz2) + (size_t)within * 3;
    int cloud = s * BATCH + within / NPTS;
    int cx = cell_coord(p[0]);
    int cy = cell_coord(p[1]);
    int cz = cell_coord(p[2]);
    atomicAdd(&g_hist[cloud][(cz * G + cy) * G + cx], 1);
}

// One block per cloud: exclusive scan of 32768 counts (1024 threads x 32 cells)
__global__ void __launch_bounds__(1024)
scan_kernel() {
    __shared__ int sh[1024];
    int cloud = blockIdx.x;
    int t = threadIdx.x;

    int cnt[32];
    int tsum = 0;
#pragma unroll
    for (int k = 0; k < 32; k++) {
        cnt[k] = g_hist[cloud][t * 32 + k];
        tsum += cnt[k];
    }
    sh[t] = tsum;
    __syncthreads();
    // Hillis-Steele inclusive scan over thread totals
    for (int off = 1; off < 1024; off <<= 1) {
        int v = (t >= off) ? sh[t - off] : 0;
        __syncthreads();
        sh[t] += v;
        __syncthreads();
    }
    int run = sh[t] - tsum;   // exclusive base for this thread's 32 cells
#pragma unroll
    for (int k = 0; k < 32; k++) {
        g_cellstart[cloud][t * 32 + k] = run;
        g_cursor[cloud][t * 32 + k]    = run;
        run += cnt[k];
    }
    if (t == 1023) g_cellstart[cloud][NCELLS] = run;   // == NPTS
}

__global__ void scatter_kernel(const float* __restrict__ xyz1,
                               const float* __restrict__ xyz2) {
    int idx = blockIdx.x * blockDim.x + threadIdx.x;
    int s      = idx / (BATCH * NPTS);
    int within = idx - s * (BATCH * NPTS);
    const float* p = ((s == 0) ? xyz1 : xyz2) + (size_t)within * 3;
    int cloud = s * BATCH + within / NPTS;
    int pid   = within % NPTS;
    float x = p[0], y = p[1], z = p[2];
    int cx = cell_coord(x);
    int cy = cell_coord(y);
    int cz = cell_coord(z);
    int cell = (cz * G + cy) * G + cx;
    int slot = atomicAdd(&g_cursor[cloud][cell], 1);
    g_pts[cloud][slot]  = make_float4(x, y, z, x * x + y * y + z * z);
    g_oidx[cloud][slot] = pid;
}

// ---------------- main query kernel ----------------

__global__ void __launch_bounds__(256)
query_kernel() {
    int tid = blockIdx.x * blockDim.x + threadIdx.x;    // 0 .. NQ-1
    int cloud_q = tid / NPTS;                           // sorted-order query cloud
    int i       = tid - cloud_q * NPTS;
    int s = cloud_q / BATCH;
    int b = cloud_q - s * BATCH;
    int cand = (s ^ 1) * BATCH + b;                     // opposite cloud, same batch

    float4 q = g_pts[cloud_q][i];
    int oi    = g_oidx[cloud_q][i];
    float n2q = q.w;
    float ax = -2.0f * q.x, ay = -2.0f * q.y, az = -2.0f * q.z;

    int cx = cell_coord(q.x);
    int cy = cell_coord(q.y);
    int cz = cell_coord(q.z);

    const float4* P = g_pts[cand];
    const int*    S = g_cellstart[cand];

    float best = CUDART_INF_F;   // min over candidates of (|y|^2 - 2 x.y)

    // r = 1: full 3x3x3 neighborhood
    for (int dz = -1; dz <= 1; dz++) {
        int zc = min(max(cz + dz, 0), G - 1);
        for (int dy = -1; dy <= 1; dy++) {
            int yc = min(max(cy + dy, 0), G - 1);
            for (int dx = -1; dx <= 1; dx++) {
                int xc = min(max(cx + dx, 0), G - 1);
                int cell = (zc * G + yc) * G + xc;
                int j0 = S[cell], j1 = S[cell + 1];
                for (int j = j0; j < j1; j++) {
                    float4 p = P[j];
                    float t = fmaf(az, p.z, p.w);
                    t = fmaf(ay, p.y, t);
                    t = fmaf(ax, p.x, t);
                    best = fminf(best, t);
                }
            }
        }
    }

    // Expand Chebyshev shells until exact-NN bound satisfied.
    int r = 1;
    while (true) {
        float d2 = n2q + best;
        float bnd = (float)r * H;
        if (d2 <= bnd * bnd || r >= G) break;
        r++;
        for (int dz = -r; dz <= r; dz++) {
            int zc = min(max(cz + dz, 0), G - 1);
            int adz = abs(dz);
            for (int dy = -r; dy <= r; dy++) {
                int yc = min(max(cy + dy, 0), G - 1);
                int ady = abs(dy);
                int inner = (adz < r) && (ady < r);
                for (int dx = -r; dx <= r; dx++) {
                    if (inner && abs(dx) < r) continue;   // only the new shell
                    int xc = min(max(cx + dx, 0), G - 1);
                    int cell = (zc * G + yc) * G + xc;
                    int j0 = S[cell], j1 = S[cell + 1];
                    for (int j = j0; j < j1; j++) {
                        float4 p = P[j];
                        float t = fmaf(az, p.z, p.w);
                        t = fmaf(ay, p.y, t);
                        t = fmaf(ax, p.x, t);
                        best = fminf(best, t);
                    }
                }
            }
        }
    }

    g_dist[cloud_q][oi] = sqrtf(fmaxf(n2q + best, EPSF));
}

// ---------------- deterministic reduction ----------------

__global__ void __launch_bounds__(1024)
reduce_kernel() {
    __shared__ float wsum[32];
    int idx = blockIdx.x * 1024 + threadIdx.x;   // NQ / 1024 = 128 blocks
    float v = ((const float*)g_dist)[idx];
#pragma unroll
    for (int o = 16; o > 0; o >>= 1)
        v += __shfl_down_sync(0xFFFFFFFFu, v, o);
    if ((threadIdx.x & 31) == 0) wsum[threadIdx.x >> 5] = v;
    __syncthreads();
    if (threadIdx.x < 32) {
        float s = wsum[threadIdx.x];
#pragma unroll
        for (int o = 16; o > 0; o >>= 1)
            s += __shfl_down_sync(0xFFFFFFFFu, s, o);
        if (threadIdx.x == 0) g_bsum[blockIdx.x] = s;
    }
}

__global__ void final_kernel(float* __restrict__ out) {
    float s = 0.0f;
#pragma unroll
    for (int i = 0; i < 128; i++) s += g_bsum[i];
    out[0] = s * (1.0f / (2.0f * BATCH * NPTS));
}

extern "C" void kernel_launch(void* const* d_in, const int* in_sizes, int n_in,
                              void* d_out, int out_size) {
    const float* xyz1 = (const float*)d_in[0];
    const float* xyz2 = (const float*)d_in[1];
    float* out = (float*)d_out;

    zero_kernel<<<(NCLOUD * NCELLS) / 1024, 1024>>>();
    hist_kernel<<<NQ / 256, 256>>>(xyz1, xyz2);
    scan_kernel<<<NCLOUD, 1024>>>();
    scatter_kernel<<<NQ / 256, 256>>>(xyz1, xyz2);
    query_kernel<<<NQ / 256, 256>>>();
    reduce_kernel<<<NQ / 1024, 1024>>>();
    final_kernel<<<1, 1>>>(out);
}

// round 4
// speedup vs baseline: 3.4693x; 3.4693x over previous
#include <cuda_runtime.h>
#include <math_constants.h>

// Fixed shapes per reference setup_inputs
#define BATCH   8
#define NPTS    8192
#define NQ      (2 * BATCH * NPTS)     // 131072 queries total
#define EPSF    1e-12f

// Grid parameters (cell hash: x fastest)
#define G       32
#define NCELLS  (G * G * G)            // 32768
#define GLO     (-4.0f)
#define H       0.25f
#define INVH    4.0f
#define NCLOUD  16                     // 2 inputs x 8 batches

#define P2_BLOCKS 256
#define P2_THREADS 256
#define P2_WARPS (P2_BLOCKS * (P2_THREADS / 32))   // 2048

// Scratch (no cudaMalloc allowed)
__device__ float4 g_pts[NCLOUD][NPTS];          // cell-sorted records (x,y,z,|p|^2)
__device__ int    g_oidx[NCLOUD][NPTS];         // original in-batch index
__device__ int    g_hist[NCLOUD][NCELLS];
__device__ int    g_cellstart[NCLOUD][NCELLS + 1];
__device__ int    g_cursor[NCLOUD][NCELLS];
__device__ float  g_dist[NCLOUD][NPTS];         // per-original-index NN distance
__device__ float  g_best[NQ];                   // phase-1 best c = |y|^2-2x.y (sorted tid)
__device__ int    g_flist[NQ];                  // unfinished query tids
__device__ int    g_fcnt;
__device__ float  g_bsum[128];

__device__ __forceinline__ int cell_coord(float v) {
    int c = (int)((v - GLO) * INVH);
    return min(max(c, 0), G - 1);
}

// ---------------- setup ----------------

__global__ void zero_kernel() {
    int idx = blockIdx.x * blockDim.x + threadIdx.x;
    if (idx == 0) g_fcnt = 0;
    ((int*)g_hist)[idx] = 0;
}

__global__ void hist_kernel(const float* __restrict__ xyz1,
                            const float* __restrict__ xyz2) {
    int idx = blockIdx.x * blockDim.x + threadIdx.x;
    int s      = idx >> 16;
    int within = idx & 0xFFFF;
    const float* p = ((s == 0) ? xyz1 : xyz2) + (size_t)within * 3;
    int cloud = s * BATCH + (within >> 13);
    int cx = cell_coord(p[0]);
    int cy = cell_coord(p[1]);
    int cz = cell_coord(p[2]);
    atomicAdd(&g_hist[cloud][(cz * G + cy) * G + cx], 1);
}

__global__ void __launch_bounds__(1024)
scan_kernel() {
    __shared__ int sh[1024];
    int cloud = blockIdx.x;
    int t = threadIdx.x;
    int cnt[32];
    int tsum = 0;
#pragma unroll
    for (int k = 0; k < 32; k++) {
        cnt[k] = g_hist[cloud][t * 32 + k];
        tsum += cnt[k];
    }
    sh[t] = tsum;
    __syncthreads();
    for (int off = 1; off < 1024; off <<= 1) {
        int v = (t >= off) ? sh[t - off] : 0;
        __syncthreads();
        sh[t] += v;
        __syncthreads();
    }
    int run = sh[t] - tsum;
#pragma unroll
    for (int k = 0; k < 32; k++) {
        g_cellstart[cloud][t * 32 + k] = run;
        g_cursor[cloud][t * 32 + k]    = run;
        run += cnt[k];
    }
    if (t == 1023) g_cellstart[cloud][NCELLS] = run;
}

__global__ void scatter_kernel(const float* __restrict__ xyz1,
                               const float* __restrict__ xyz2) {
    int idx = blockIdx.x * blockDim.x + threadIdx.x;
    int s      = idx >> 16;
    int within = idx & 0xFFFF;
    const float* p = ((s == 0) ? xyz1 : xyz2) + (size_t)within * 3;
    int cloud = s * BATCH + (within >> 13);
    int pid   = within & (NPTS - 1);
    float x = p[0], y = p[1], z = p[2];
    int cell = (cell_coord(z) * G + cell_coord(y)) * G + cell_coord(x);
    int slot = atomicAdd(&g_cursor[cloud][cell], 1);
    g_pts[cloud][slot]  = make_float4(x, y, z, x * x + y * y + z * z);
    g_oidx[cloud][slot] = pid;
}

// ---------------- phase 1: 3x3x3 scan, common case ----------------

__global__ void __launch_bounds__(256)
phase1_kernel() {
    int tid = blockIdx.x * 256 + threadIdx.x;      // sorted query id
    int cloud_q = tid >> 13;
    int i       = tid & (NPTS - 1);
    int cand    = cloud_q ^ 8;                     // opposite input, same batch

    float4 q = g_pts[cloud_q][i];
    float n2q = q.w;
    float ax = -2.0f * q.x, ay = -2.0f * q.y, az = -2.0f * q.z;
    int cx = cell_coord(q.x);
    int cy = cell_coord(q.y);
    int cz = cell_coord(q.z);

    const float4* __restrict__ P = g_pts[cand];
    const int*    __restrict__ S = g_cellstart[cand];

    int x0 = max(cx - 1, 0);
    int x1 = min(cx + 1, G - 1);

    float best = CUDART_INF_F;
#pragma unroll
    for (int dz = -1; dz <= 1; dz++) {
        int zc = cz + dz;
        bool zok = ((unsigned)zc < G);
#pragma unroll
        for (int dy = -1; dy <= 1; dy++) {
            int yc = cy + dy;
            int j0 = 0, j1 = 0;
            if (zok && ((unsigned)yc < G)) {
                int row = (zc * G + yc) * G;
                j0 = S[row + x0];
                j1 = S[row + x1 + 1];   // 3 x-cells contiguous in sorted order
            }
            for (int j = j0; j < j1; j++) {
                float4 p = P[j];
                float t = fmaf(az, p.z, p.w);
                t = fmaf(ay, p.y, t);
                t = fmaf(ax, p.x, t);
                best = fminf(best, t);
            }
        }
    }

    float d2 = n2q + best;
    int oi = g_oidx[cloud_q][i];
    g_dist[cloud_q][oi] = sqrtf(fmaxf(d2, EPSF));

    if (!(d2 <= H * H)) {                          // rare tail (also catches inf)
        g_best[tid] = best;
        int slot = atomicAdd(&g_fcnt, 1);
        g_flist[slot] = tid;
    }
}

// ---------------- phase 2: warp-cooperative shell expansion ----------------

__global__ void __launch_bounds__(P2_THREADS)
phase2_kernel() {
    int wg   = blockIdx.x * (P2_THREADS / 32) + (threadIdx.x >> 5);
    int lane = threadIdx.x & 31;
    int n = g_fcnt;

    for (int e = wg; e < n; e += P2_WARPS) {
        int tid = g_flist[e];
        int cloud_q = tid >> 13;
        int i       = tid & (NPTS - 1);
        int cand    = cloud_q ^ 8;

        float4 q = g_pts[cloud_q][i];
        float n2q = q.w;
        float ax = -2.0f * q.x, ay = -2.0f * q.y, az = -2.0f * q.z;
        int cx = cell_coord(q.x);
        int cy = cell_coord(q.y);
        int cz = cell_coord(q.z);

        const float4* __restrict__ P = g_pts[cand];
        const int*    __restrict__ S = g_cellstart[cand];

        float best = g_best[tid];
        int r = 1;
        while (r < G) {
            float d2  = n2q + best;
            float bnd = (float)r * H;
            if (d2 <= bnd * bnd) break;
            r++;
            int w  = 2 * r + 1;
            int w2 = w * w;
            int w3 = w2 * w;
            float lb = CUDART_INF_F;
            for (int idx = lane; idx < w3; idx += 32) {
                int dz = idx / w2;
                int rem = idx - dz * w2;
                int dy = rem / w;
                int dx = rem - dy * w;
                dz -= r; dy -= r; dx -= r;
                if (max(abs(dx), max(abs(dy), abs(dz))) < r) continue;  // shell only
                int zc = cz + dz, yc = cy + dy, xc = cx + dx;
                if ((unsigned)zc >= G || (unsigned)yc >= G || (unsigned)xc >= G) continue;
                int cell = (zc * G + yc) * G + xc;
                int j0 = S[cell], j1 = S[cell + 1];
                for (int j = j0; j < j1; j++) {
                    float4 p = P[j];
                    float t = fmaf(az, p.z, p.w);
                    t = fmaf(ay, p.y, t);
                    t = fmaf(ax, p.x, t);
                    lb = fminf(lb, t);
                }
            }
#pragma unroll
            for (int o = 16; o > 0; o >>= 1)
                lb = fminf(lb, __shfl_xor_sync(0xFFFFFFFFu, lb, o));
            best = fminf(best, lb);                // uniform across warp
        }
        if (lane == 0) {
            int oi = g_oidx[cloud_q][i];
            g_dist[cloud_q][oi] = sqrtf(fmaxf(n2q + best, EPSF));
        }
    }
}

// ---------------- deterministic reduction ----------------

__global__ void __launch_bounds__(1024)
reduce_kernel() {
    __shared__ float wsum[32];
    int idx = blockIdx.x * 1024 + threadIdx.x;
    float v = ((const float*)g_dist)[idx];
#pragma unroll
    for (int o = 16; o > 0; o >>= 1)
        v += __shfl_down_sync(0xFFFFFFFFu, v, o);
    if ((threadIdx.x & 31) == 0) wsum[threadIdx.x >> 5] = v;
    __syncthreads();
    if (threadIdx.x < 32) {
        float s = wsum[threadIdx.x];
#pragma unroll
        for (int o = 16; o > 0; o >>= 1)
            s += __shfl_down_sync(0xFFFFFFFFu, s, o);
        if (threadIdx.x == 0) g_bsum[blockIdx.x] = s;
    }
}

__global__ void final_kernel(float* __restrict__ out) {
    float s = 0.0f;
#pragma unroll
    for (int i = 0; i < 128; i++) s += g_bsum[i];
    out[0] = s * (1.0f / (2.0f * BATCH * NPTS));
}

extern "C" void kernel_launch(void* const* d_in, const int* in_sizes, int n_in,
                              void* d_out, int out_size) {
    const float* xyz1 = (const float*)d_in[0];
    const float* xyz2 = (const float*)d_in[1];
    float* out = (float*)d_out;

    zero_kernel<<<(NCLOUD * NCELLS) / 1024, 1024>>>();
    hist_kernel<<<NQ / 256, 256>>>(xyz1, xyz2);
    scan_kernel<<<NCLOUD, 1024>>>();
    scatter_kernel<<<NQ / 256, 256>>>(xyz1, xyz2);
    phase1_kernel<<<NQ / 256, 256>>>();
    phase2_kernel<<<P2_BLOCKS, P2_THREADS>>>();
    reduce_kernel<<<NQ / 1024, 1024>>>();
    final_kernel<<<1, 1>>>(out);
}

// round 5
// speedup vs baseline: 6.2470x; 1.8007x over previous
#include <cuda_runtime.h>
#include <math_constants.h>

// Fixed shapes per reference setup_inputs
#define BATCH   8
#define NPTS    8192
#define NQ      (2 * BATCH * NPTS)     // 131072 queries total
#define EPSF    1e-12f

// Grid parameters (cell hash: x fastest)
#define G       32
#define NCELLS  (G * G * G)            // 32768
#define GLO     (-4.0f)
#define H       0.25f
#define INVH    4.0f
#define NCLOUD  16                     // 2 inputs x 8 batches

#define P2_BLOCKS 256
#define P2_THREADS 256
#define P2_WARPS (P2_BLOCKS * (P2_THREADS / 32))   // 2048

// Scratch (no cudaMalloc allowed)
__device__ float4 g_pts[NCLOUD][NPTS];          // cell-sorted records (x,y,z,|p|^2)
__device__ int    g_oidx[NCLOUD][NPTS];         // original in-batch index
__device__ int    g_hist[NCLOUD][NCELLS];
__device__ int    g_cellstart[NCLOUD][NCELLS + 1];
__device__ int    g_cursor[NCLOUD][NCELLS];
__device__ float  g_dist[NCLOUD][NPTS];         // per-original-index NN distance
__device__ float  g_best[NQ];                   // phase-1 best c = |y|^2-2x.y
__device__ int    g_flist[NQ];                  // unfinished query tids
__device__ int    g_fcnt;
__device__ float  g_bsum[128];

__device__ __forceinline__ int cell_coord(float v) {
    int c = (int)((v - GLO) * INVH);
    return min(max(c, 0), G - 1);
}

// ---------------- setup ----------------

__global__ void zero_kernel() {
    int idx = blockIdx.x * blockDim.x + threadIdx.x;
    if (idx == 0) g_fcnt = 0;
    ((int*)g_hist)[idx] = 0;
}

__global__ void hist_kernel(const float* __restrict__ xyz1,
                            const float* __restrict__ xyz2) {
    int idx = blockIdx.x * blockDim.x + threadIdx.x;
    int s      = idx >> 16;
    int within = idx & 0xFFFF;
    const float* p = ((s == 0) ? xyz1 : xyz2) + (size_t)within * 3;
    int cloud = s * BATCH + (within >> 13);
    int cx = cell_coord(p[0]);
    int cy = cell_coord(p[1]);
    int cz = cell_coord(p[2]);
    atomicAdd(&g_hist[cloud][(cz * G + cy) * G + cx], 1);
}

__global__ void __launch_bounds__(1024)
scan_kernel() {
    __shared__ int sh[1024];
    int cloud = blockIdx.x;
    int t = threadIdx.x;
    int cnt[32];
    int tsum = 0;
#pragma unroll
    for (int k = 0; k < 32; k++) {
        cnt[k] = g_hist[cloud][t * 32 + k];
        tsum += cnt[k];
    }
    sh[t] = tsum;
    __syncthreads();
    for (int off = 1; off < 1024; off <<= 1) {
        int v = (t >= off) ? sh[t - off] : 0;
        __syncthreads();
        sh[t] += v;
        __syncthreads();
    }
    int run = sh[t] - tsum;
#pragma unroll
    for (int k = 0; k < 32; k++) {
        g_cellstart[cloud][t * 32 + k] = run;
        g_cursor[cloud][t * 32 + k]    = run;
        run += cnt[k];
    }
    if (t == 1023) g_cellstart[cloud][NCELLS] = run;
}

__global__ void scatter_kernel(const float* __restrict__ xyz1,
                               const float* __restrict__ xyz2) {
    int idx = blockIdx.x * blockDim.x + threadIdx.x;
    int s      = idx >> 16;
    int within = idx & 0xFFFF;
    const float* p = ((s == 0) ? xyz1 : xyz2) + (size_t)within * 3;
    int cloud = s * BATCH + (within >> 13);
    int pid   = within & (NPTS - 1);
    float x = p[0], y = p[1], z = p[2];
    int cell = (cell_coord(z) * G + cell_coord(y)) * G + cell_coord(x);
    int slot = atomicAdd(&g_cursor[cloud][cell], 1);
    g_pts[cloud][slot]  = make_float4(x, y, z, x * x + y * y + z * z);
    g_oidx[cloud][slot] = pid;
}

// ---------------- phase 1: 3x3x3 scan, common case ----------------

__global__ void __launch_bounds__(256)
phase1_kernel() {
    int tid = blockIdx.x * 256 + threadIdx.x;      // sorted query id
    int cloud_q = tid >> 13;
    int i       = tid & (NPTS - 1);
    int cand    = cloud_q ^ 8;                     // opposite input, same batch

    float4 q = g_pts[cloud_q][i];
    float n2q = q.w;
    float ax = -2.0f * q.x, ay = -2.0f * q.y, az = -2.0f * q.z;
    int cx = cell_coord(q.x);
    int cy = cell_coord(q.y);
    int cz = cell_coord(q.z);

    const float4* __restrict__ P = g_pts[cand];
    const int*    __restrict__ S = g_cellstart[cand];

    int x0 = max(cx - 1, 0);
    int x1 = min(cx + 1, G - 1);

    // Hoist all 9 row ranges: 18 independent header LDGs (high MLP)
    int j0a[9], j1a[9];
#pragma unroll
    for (int k = 0; k < 9; k++) {
        int dz = k / 3 - 1;
        int dy = k - (k / 3) * 3 - 1;
        int zc = cz + dz, yc = cy + dy;
        bool ok = ((unsigned)zc < G) && ((unsigned)yc < G);
        int row = (zc * G + yc) * G;
        j0a[k] = ok ? S[row + x0] : 0;
        j1a[k] = ok ? S[row + x1 + 1] : 0;
    }

    float best = CUDART_INF_F;
#pragma unroll
    for (int k = 0; k < 9; k++) {
        for (int j = j0a[k]; j < j1a[k]; j++) {
            float4 p = P[j];
            float t = fmaf(az, p.z, p.w);
            t = fmaf(ay, p.y, t);
            t = fmaf(ax, p.x, t);
            best = fminf(best, t);
        }
    }

    float d2 = n2q + best;
    int oi = g_oidx[cloud_q][i];
    g_dist[cloud_q][oi] = sqrtf(fmaxf(d2, EPSF));

    if (!(d2 <= H * H)) {                          // rare tail (also catches inf)
        g_best[tid] = best;
        int slot = atomicAdd(&g_fcnt, 1);
        g_flist[slot] = tid;
    }
}

// ---------------- phase 2: warp-cooperative row-based shell expansion ----------------

__global__ void __launch_bounds__(P2_THREADS)
phase2_kernel() {
    int wg   = blockIdx.x * (P2_THREADS / 32) + (threadIdx.x >> 5);
    int lane = threadIdx.x & 31;
    int n = g_fcnt;

    for (int e = wg; e < n; e += P2_WARPS) {
        int tid = g_flist[e];
        int cloud_q = tid >> 13;
        int i       = tid & (NPTS - 1);
        int cand    = cloud_q ^ 8;

        float4 q = g_pts[cloud_q][i];
        float n2q = q.w;
        float ax = -2.0f * q.x, ay = -2.0f * q.y, az = -2.0f * q.z;
        int cx = cell_coord(q.x);
        int cy = cell_coord(q.y);
        int cz = cell_coord(q.z);

        const float4* __restrict__ P = g_pts[cand];
        const int*    __restrict__ S = g_cellstart[cand];

        float best = g_best[tid];
        int r = 1;
        while (r < G) {
            float d2  = n2q + best;
            float bnd = (float)r * H;
            if (d2 <= bnd * bnd) break;
            r++;
            int w  = 2 * r + 1;
            int w2 = w * w;
            float lb = CUDART_INF_F;
            // Lane-parallel over the w^2 (dz,dy) rows of this shell.
            for (int idx = lane; idx < w2; idx += 32) {
                int dz = idx / w - r;
                int dy = idx - (idx / w) * w - r;
                int zc = cz + dz, yc = cy + dy;
                if ((unsigned)zc >= G || (unsigned)yc >= G) continue;
                int row = (zc * G + yc) * G;
                bool boundary = (abs(dz) == r) || (abs(dy) == r);
                if (boundary) {
                    // full x-extent of this row: ONE contiguous sorted range
                    int bx0 = max(cx - r, 0);
                    int bx1 = min(cx + r, G - 1);
                    int j0 = S[row + bx0], j1 = S[row + bx1 + 1];
                    for (int j = j0; j < j1; j++) {
                        float4 p = P[j];
                        float t = fmaf(az, p.z, p.w);
                        t = fmaf(ay, p.y, t);
                        t = fmaf(ax, p.x, t);
                        lb = fminf(lb, t);
                    }
                } else {
                    // interior row: only the two dx = +-r cells
                    int xm = cx - r;
                    if (xm >= 0) {
                        int j0 = S[row + xm], j1 = S[row + xm + 1];
                        for (int j = j0; j < j1; j++) {
                            float4 p = P[j];
                            float t = fmaf(az, p.z, p.w);
                            t = fmaf(ay, p.y, t);
                            t = fmaf(ax, p.x, t);
                            lb = fminf(lb, t);
                        }
                    }
                    int xp = cx + r;
                    if (xp < G) {
                        int j0 = S[row + xp], j1 = S[row + xp + 1];
                        for (int j = j0; j < j1; j++) {
                            float4 p = P[j];
                            float t = fmaf(az, p.z, p.w);
                            t = fmaf(ay, p.y, t);
                            t = fmaf(ax, p.x, t);
                            lb = fminf(lb, t);
                        }
                    }
                }
            }
#pragma unroll
            for (int o = 16; o > 0; o >>= 1)
                lb = fminf(lb, __shfl_xor_sync(0xFFFFFFFFu, lb, o));
            best = fminf(best, lb);                // uniform across warp
        }
        if (lane == 0) {
            int oi = g_oidx[cloud_q][i];
            g_dist[cloud_q][oi] = sqrtf(fmaxf(n2q + best, EPSF));
        }
    }
}

// ---------------- deterministic reduction ----------------

__global__ void __launch_bounds__(1024)
reduce_kernel() {
    __shared__ float wsum[32];
    int idx = blockIdx.x * 1024 + threadIdx.x;
    float v = ((const float*)g_dist)[idx];
#pragma unroll
    for (int o = 16; o > 0; o >>= 1)
        v += __shfl_down_sync(0xFFFFFFFFu, v, o);
    if ((threadIdx.x & 31) == 0) wsum[threadIdx.x >> 5] = v;
    __syncthreads();
    if (threadIdx.x < 32) {
        float s = wsum[threadIdx.x];
#pragma unroll
        for (int o = 16; o > 0; o >>= 1)
            s += __shfl_down_sync(0xFFFFFFFFu, s, o);
        if (threadIdx.x == 0) g_bsum[blockIdx.x] = s;
    }
}

__global__ void final_kernel(float* __restrict__ out) {
    float s = 0.0f;
#pragma unroll
    for (int i = 0; i < 128; i++) s += g_bsum[i];
    out[0] = s * (1.0f / (2.0f * BATCH * NPTS));
}

extern "C" void kernel_launch(void* const* d_in, const int* in_sizes, int n_in,
                              void* d_out, int out_size) {
    const float* xyz1 = (const float*)d_in[0];
    const float* xyz2 = (const float*)d_in[1];
    float* out = (float*)d_out;

    zero_kernel<<<(NCLOUD * NCELLS) / 1024, 1024>>>();
    hist_kernel<<<NQ / 256, 256>>>(xyz1, xyz2);
    scan_kernel<<<NCLOUD, 1024>>>();
    scatter_kernel<<<NQ / 256, 256>>>(xyz1, xyz2);
    phase1_kernel<<<NQ / 256, 256>>>();
    phase2_kernel<<<P2_BLOCKS, P2_THREADS>>>();
    reduce_kernel<<<NQ / 1024, 1024>>>();
    final_kernel<<<1, 1>>>(out);
}

// round 6
// speedup vs baseline: 6.6071x; 1.0576x over previous
#include <cuda_runtime.h>
#include <math_constants.h>

// Fixed shapes per reference setup_inputs
#define BATCH   8
#define NPTS    8192
#define NQ      (2 * BATCH * NPTS)     // 131072 queries total
#define EPSF    1e-12f
#define SCALE   (1.0f / 131072.0f)     // 1/(2*BATCH*NPTS)

// Grid parameters (cell hash: x fastest)
#define G       32
#define NCELLS  (G * G * G)            // 32768
#define GLO     (-4.0f)
#define H       0.25f
#define INVH    4.0f
#define NCLOUD  16                     // 2 inputs x 8 batches

#define P2_BLOCKS 256
#define P2_THREADS 256
#define P2_WARPS (P2_BLOCKS * (P2_THREADS / 32))   // 2048

// Scratch (no cudaMalloc allowed). All zero-initialized at module load;
// g_hist and g_fcnt are re-zeroed by the pipeline itself for the next call.
__device__ float4 g_pts[NCLOUD][NPTS];          // cell-sorted records (x,y,z,|p|^2)
__device__ int    g_hist[NCLOUD][NCELLS];
__device__ int    g_cellstart[NCLOUD][NCELLS + 1];
__device__ int    g_cursor[NCLOUD][NCELLS];
__device__ float  g_best[NQ];                   // phase-1 best c = |y|^2-2x.y
__device__ int    g_flist[NQ];                  // unfinished query tids
__device__ int    g_fcnt;

__device__ __forceinline__ int cell_coord(float v) {
    int c = (int)((v - GLO) * INVH);
    return min(max(c, 0), G - 1);
}

// ---------------- 1. hist (+ init out, fcnt) ----------------

__global__ void hist_kernel(const float* __restrict__ xyz1,
                            const float* __restrict__ xyz2,
                            float* __restrict__ out) {
    int idx = blockIdx.x * blockDim.x + threadIdx.x;
    if (idx == 0) { out[0] = 0.0f; g_fcnt = 0; }
    int s      = idx >> 16;
    int within = idx & 0xFFFF;
    const float* p = ((s == 0) ? xyz1 : xyz2) + (size_t)within * 3;
    int cloud = s * BATCH + (within >> 13);
    int cx = cell_coord(p[0]);
    int cy = cell_coord(p[1]);
    int cz = cell_coord(p[2]);
    atomicAdd(&g_hist[cloud][(cz * G + cy) * G + cx], 1);
}

// ---------------- 2. scan (2-barrier shfl version) ----------------

__global__ void __launch_bounds__(1024)
scan_kernel() {
    __shared__ int wsum[32];
    int cloud = blockIdx.x;
    int t    = threadIdx.x;
    int lane = t & 31;
    int warp = t >> 5;

    int cnt[32];
    int tsum = 0;
#pragma unroll
    for (int k = 0; k < 32; k++) {
        cnt[k] = g_hist[cloud][t * 32 + k];
        tsum += cnt[k];
    }
    // inclusive warp scan of per-thread totals
    int v = tsum;
#pragma unroll
    for (int o = 1; o < 32; o <<= 1) {
        int u = __shfl_up_sync(0xFFFFFFFFu, v, o);
        if (lane >= o) v += u;
    }
    if (lane == 31) wsum[warp] = v;
    __syncthreads();
    if (warp == 0) {
        int w = wsum[lane];
#pragma unroll
        for (int o = 1; o < 32; o <<= 1) {
            int u = __shfl_up_sync(0xFFFFFFFFu, w, o);
            if (lane >= o) w += u;
        }
        wsum[lane] = w;
    }
    __syncthreads();
    int run = ((warp > 0) ? wsum[warp - 1] : 0) + v - tsum;   // exclusive base
#pragma unroll
    for (int k = 0; k < 32; k++) {
        g_cellstart[cloud][t * 32 + k] = run;
        g_cursor[cloud][t * 32 + k]    = run;
        run += cnt[k];
    }
    if (t == 1023) g_cellstart[cloud][NCELLS] = run;   // == NPTS
}

// ---------------- 3. scatter ----------------

__global__ void scatter_kernel(const float* __restrict__ xyz1,
                               const float* __restrict__ xyz2) {
    int idx = blockIdx.x * blockDim.x + threadIdx.x;
    int s      = idx >> 16;
    int within = idx & 0xFFFF;
    const float* p = ((s == 0) ? xyz1 : xyz2) + (size_t)within * 3;
    int cloud = s * BATCH + (within >> 13);
    float x = p[0], y = p[1], z = p[2];
    int cell = (cell_coord(z) * G + cell_coord(y)) * G + cell_coord(x);
    int slot = atomicAdd(&g_cursor[cloud][cell], 1);
    g_pts[cloud][slot] = make_float4(x, y, z, x * x + y * y + z * z);
}

// ---------------- 4. phase 1: 3x3x3 scan + fused partial sum ----------------
// Also re-zeroes g_hist for the next invocation (scan already consumed it).

__global__ void __launch_bounds__(256)
phase1_kernel(float* __restrict__ out) {
    __shared__ float blksum[8];
    int tid = blockIdx.x * 256 + threadIdx.x;      // sorted query id

    // re-zero hist for next call: 131072 threads x int4
    ((int4*)g_hist)[tid] = make_int4(0, 0, 0, 0);

    int cloud_q = tid >> 13;
    int i       = tid & (NPTS - 1);
    int cand    = cloud_q ^ 8;                     // opposite input, same batch

    float4 q = g_pts[cloud_q][i];
    float n2q = q.w;
    float ax = -2.0f * q.x, ay = -2.0f * q.y, az = -2.0f * q.z;
    int cx = cell_coord(q.x);
    int cy = cell_coord(q.y);
    int cz = cell_coord(q.z);

    const float4* __restrict__ P = g_pts[cand];
    const int*    __restrict__ S = g_cellstart[cand];

    int x0 = max(cx - 1, 0);
    int x1 = min(cx + 1, G - 1);

    // Hoist all 9 row ranges: 18 independent header LDGs (high MLP)
    int j0a[9], j1a[9];
#pragma unroll
    for (int k = 0; k < 9; k++) {
        int dz = k / 3 - 1;
        int dy = k - (k / 3) * 3 - 1;
        int zc = cz + dz, yc = cy + dy;
        bool ok = ((unsigned)zc < G) && ((unsigned)yc < G);
        int row = (zc * G + yc) * G;
        j0a[k] = ok ? S[row + x0] : 0;
        j1a[k] = ok ? S[row + x1 + 1] : 0;
    }

    float best = CUDART_INF_F;
#pragma unroll
    for (int k = 0; k < 9; k++) {
        for (int j = j0a[k]; j < j1a[k]; j++) {
            float4 p = P[j];
            float t = fmaf(az, p.z, p.w);
            t = fmaf(ay, p.y, t);
            t = fmaf(ax, p.x, t);
            best = fminf(best, t);
        }
    }

    float d2 = n2q + best;
    float contrib = 0.0f;
    if (d2 <= H * H) {
        contrib = sqrtf(fmaxf(d2, EPSF));          // finished here
    } else {                                       // rare tail (also catches inf)
        g_best[tid] = best;
        int slot = atomicAdd(&g_fcnt, 1);
        g_flist[slot] = tid;
    }

    // block-reduce finished contributions -> one atomicAdd per block
#pragma unroll
    for (int o = 16; o > 0; o >>= 1)
        contrib += __shfl_down_sync(0xFFFFFFFFu, contrib, o);
    if ((threadIdx.x & 31) == 0) blksum[threadIdx.x >> 5] = contrib;
    __syncthreads();
    if (threadIdx.x == 0) {
        float s = 0.0f;
#pragma unroll
        for (int w = 0; w < 8; w++) s += blksum[w];
        atomicAdd(out, s * SCALE);
    }
}

// ---------------- 5. phase 2: warp-cooperative shell expansion + add ----------------

__global__ void __launch_bounds__(P2_THREADS)
phase2_kernel(float* __restrict__ out) {
    int wg   = blockIdx.x * (P2_THREADS / 32) + (threadIdx.x >> 5);
    int lane = threadIdx.x & 31;
    int n = g_fcnt;

    for (int e = wg; e < n; e += P2_WARPS) {
        int tid = g_flist[e];
        int cloud_q = tid >> 13;
        int i       = tid & (NPTS - 1);
        int cand    = cloud_q ^ 8;

        float4 q = g_pts[cloud_q][i];
        float n2q = q.w;
        float ax = -2.0f * q.x, ay = -2.0f * q.y, az = -2.0f * q.z;
        int cx = cell_coord(q.x);
        int cy = cell_coord(q.y);
        int cz = cell_coord(q.z);

        const float4* __restrict__ P = g_pts[cand];
        const int*    __restrict__ S = g_cellstart[cand];

        float best = g_best[tid];
        int r = 1;
        while (r < G) {
            float d2  = n2q + best;
            float bnd = (float)r * H;
            if (d2 <= bnd * bnd) break;
            r++;
            int w  = 2 * r + 1;
            int w2 = w * w;
            float lb = CUDART_INF_F;
            // Lane-parallel over the w^2 (dz,dy) rows of this shell.
            for (int idx = lane; idx < w2; idx += 32) {
                int dz = idx / w - r;
                int dy = idx - (idx / w) * w - r;
                int zc = cz + dz, yc = cy + dy;
                if ((unsigned)zc >= G || (unsigned)yc >= G) continue;
                int row = (zc * G + yc) * G;
                bool boundary = (abs(dz) == r) || (abs(dy) == r);
                if (boundary) {
                    // full x-extent of this row: ONE contiguous sorted range
                    int bx0 = max(cx - r, 0);
                    int bx1 = min(cx + r, G - 1);
                    int j0 = S[row + bx0], j1 = S[row + bx1 + 1];
                    for (int j = j0; j < j1; j++) {
                        float4 p = P[j];
                        float t = fmaf(az, p.z, p.w);
                        t = fmaf(ay, p.y, t);
                        t = fmaf(ax, p.x, t);
                        lb = fminf(lb, t);
                    }
                } else {
                    // interior row: only the two dx = +-r cells
                    int xm = cx - r;
                    if (xm >= 0) {
                        int j0 = S[row + xm], j1 = S[row + xm + 1];
                        for (int j = j0; j < j1; j++) {
                            float4 p = P[j];
                            float t = fmaf(az, p.z, p.w);
                            t = fmaf(ay, p.y, t);
                            t = fmaf(ax, p.x, t);
                            lb = fminf(lb, t);
                        }
                    }
                    int xp = cx + r;
                    if (xp < G) {
                        int j0 = S[row + xp], j1 = S[row + xp + 1];
                        for (int j = j0; j < j1; j++) {
                            float4 p = P[j];
                            float t = fmaf(az, p.z, p.w);
                            t = fmaf(ay, p.y, t);
                            t = fmaf(ax, p.x, t);
                            lb = fminf(lb, t);
                        }
                    }
                }
            }
#pragma unroll
            for (int o = 16; o > 0; o >>= 1)
                lb = fminf(lb, __shfl_xor_sync(0xFFFFFFFFu, lb, o));
            best = fminf(best, lb);                // uniform across warp
        }
        if (lane == 0)
            atomicAdd(out, sqrtf(fmaxf(n2q + best, EPSF)) * SCALE);
    }
}

extern "C" void kernel_launch(void* const* d_in, const int* in_sizes, int n_in,
                              void* d_out, int out_size) {
    const float* xyz1 = (const float*)d_in[0];
    const float* xyz2 = (const float*)d_in[1];
    float* out = (float*)d_out;

    hist_kernel<<<NQ / 256, 256>>>(xyz1, xyz2, out);
    scan_kernel<<<NCLOUD, 1024>>>();
    scatter_kernel<<<NQ / 256, 256>>>(xyz1, xyz2);
    phase1_kernel<<<NQ / 256, 256>>>(out);
    phase2_kernel<<<P2_BLOCKS, P2_THREADS>>>(out);
}